// round 17
// baseline (speedup 1.0000x reference)
#include <cuda_runtime.h>
#include <cuda_bf16.h>
#include <math.h>

#define NN     4096
#define BB     8
#define NPG    512
#define KK     30
#define NBASIS 32
#define EDIM   35      // NBASIS + 3
#define HH     256
#define X2H    512
#define TT     128
#define LL     5
#define RADIUS 1.5f

// ---------------- static scratch (no allocations allowed) ----------------
__device__ __align__(16) float d_tfeat[BB * TT];
__device__ __align__(16) float d_tproj[LL * BB * HH];
__device__ __align__(16) float d_h[NN * HH];
__device__ __align__(16) float d_aggr[NN * X2H];
__device__ __align__(16) float d_z1[NN * HH];
__device__ __align__(16) float d_z[NN * HH];
// bf16x2-packed fragments, hi | lo
__device__ __align__(16) unsigned d_afrag[(NN / 16) * 24576]; // edge A frags per 16-node block
__device__ __align__(16) unsigned d_bfrag[LL * 4 * 6144];     // edge B frags per (layer, chunk)
__device__ __align__(16) unsigned d_w1frag[LL * 32 * 4096];   // W1 frags (hi | lo per layer)
__device__ __align__(16) unsigned d_w2frag[LL * 16 * 4096];   // W2 frags
__device__ int   d_nbr[NN * KK];
__device__ int   d_cnt[NN];
__device__ float d_elen[NN * KK];
__device__ __align__(16) float d_psum[64 * HH];   // gemm1 per-mblock col sums
__device__ __align__(16) float d_psumq[64 * HH];  // gemm1 per-mblock col sumsq

__device__ __forceinline__ float silu_f(float v) { return v / (1.f + expf(-v)); }

// ---------------- bf16 helpers ----------------
__device__ __forceinline__ unsigned pack_bf16x2(float a, float b) {
    __nv_bfloat162 h = __floats2bfloat162_rn(a, b);
    return *(unsigned*)&h;
}
__device__ __forceinline__ void mma_bf16(float* c, uint4 a, unsigned b0, unsigned b1) {
    asm volatile(
        "mma.sync.aligned.m16n8k16.row.col.f32.bf16.bf16.f32 "
        "{%0,%1,%2,%3}, {%4,%5,%6,%7}, {%8,%9}, {%0,%1,%2,%3};"
        : "+f"(c[0]), "+f"(c[1]), "+f"(c[2]), "+f"(c[3])
        : "r"(a.x), "r"(a.y), "r"(a.z), "r"(a.w), "r"(b0), "r"(b1));
}

// ---------------- time embedding ----------------
__global__ void k_temb(const float* __restrict__ tin, const float* __restrict__ wgfp,
                       const float* __restrict__ wt, const float* __restrict__ bt) {
    __shared__ float ss[64], sc[64];
    int t = threadIdx.x; // 128
    for (int b = 0; b < BB; b++) {
        if (t < 64) {
            float xp = 6.283185307179586f * tin[b] * wgfp[t];
            ss[t] = sinf(xp);
            sc[t] = cosf(xp);
        }
        __syncthreads();
        float acc = bt[t];
        #pragma unroll 8
        for (int h = 0; h < 64; h++) {
            acc = fmaf(ss[h], wt[h * TT + t], acc);
            acc = fmaf(sc[h], wt[(64 + h) * TT + t], acc);
        }
        d_tfeat[b * TT + t] = silu_f(acc);
        __syncthreads();
    }
}

__global__ void k_tproj(const float* __restrict__ Wt, const float* __restrict__ bt) {
    int l = blockIdx.x / BB, b = blockIdx.x % BB;
    int c = threadIdx.x; // 256
    __shared__ float tf[TT];
    if (c < TT) tf[c] = d_tfeat[b * TT + c];
    __syncthreads();
    float acc = bt[l * HH + c];
    const float* w = Wt + (size_t)l * TT * HH;
    #pragma unroll 8
    for (int k = 0; k < TT; k++) acc = fmaf(tf[k], w[k * HH + c], acc);
    d_tproj[(l * BB + b) * HH + c] = acc;
}

__global__ void k_hin(const float* __restrict__ coords, const float* __restrict__ Win,
                      const float* __restrict__ bin) {
    int i = blockIdx.x;
    int c = threadIdx.x;
    float x0 = coords[i * 3 + 0], x1 = coords[i * 3 + 1], x2 = coords[i * 3 + 2];
    float v = fmaf(x0, Win[c], fmaf(x1, Win[HH + c], fmaf(x2, Win[2 * HH + c], bin[c])));
    d_h[(size_t)i * HH + c] = v;
}

// ---------------- radius graph (stores selected distances too) ------------
__global__ void __launch_bounds__(128) k_nbr(const float* __restrict__ coords) {
    __shared__ float sx[NPG], sy[NPG], sz[NPG];
    __shared__ float sd[4][NPG];
    int t = threadIdx.x;
    int base = blockIdx.x * 4;
    int goff = (base >> 9) << 9;
    for (int j = t; j < NPG; j += 128) {
        sx[j] = coords[(goff + j) * 3 + 0];
        sy[j] = coords[(goff + j) * 3 + 1];
        sz[j] = coords[(goff + j) * 3 + 2];
    }
    __syncthreads();
    int w = t >> 5, lane = t & 31;
    int il = (base & 511) + w;
    int ig = goff + il;
    float xi = sx[il], yi = sy[il], zi = sz[il];
    float sqi = xi * xi + yi * yi + zi * zi;
    for (int j = lane; j < NPG; j += 32) {
        float xj = sx[j], yj = sy[j], zj = sz[j];
        float dot = xi * xj + yi * yj + zi * zj;
        float sqj = xj * xj + yj * yj + zj * zj;
        float d2 = sqi + sqj - 2.f * dot;
        float d = sqrtf(fmaxf(d2, 1e-12f));
        sd[w][j] = (j != il && d < RADIUS) ? d : INFINITY;
    }
    __syncwarp();
    int cc = 0;
    for (int k = 0; k < KK; k++) {
        float best = INFINITY;
        int bi = -1;
        for (int j = lane; j < NPG; j += 32) {
            float v = sd[w][j];
            if (v < best) { best = v; bi = j; }
        }
        #pragma unroll
        for (int off = 16; off; off >>= 1) {
            float ov = __shfl_down_sync(0xffffffffu, best, off);
            int oi = __shfl_down_sync(0xffffffffu, bi, off);
            if (ov < best || (ov == best && (unsigned)oi < (unsigned)bi)) { best = ov; bi = oi; }
        }
        best = __shfl_sync(0xffffffffu, best, 0);
        bi = __shfl_sync(0xffffffffu, bi, 0);
        if (!(best < INFINITY)) break;
        if (lane == 0) {
            d_nbr[ig * KK + k] = goff + bi;
            d_elen[ig * KK + k] = best;
            sd[w][bi] = INFINITY;
        }
        cc = k + 1;
        __syncwarp();
    }
    if (lane == 0) d_cnt[ig] = cc;
}

// ---------------- A fragments: edge attrs, 16-node blocks -----------------
__global__ void __launch_bounds__(256) k_afrag(const float* __restrict__ coords) {
    int blk = blockIdx.x;            // 256 blocks of 16 nodes
    int i0 = blk * 16;
    unsigned* outp = d_afrag + (size_t)blk * 24576;
    const float step = RADIUS / 33.f;
    const float istep = 33.f / RADIUS;
    for (int idx = threadIdx.x; idx < 12288; idx += 256) {
        int r = idx & 3;
        int lane = (idx >> 2) & 31;
        int ks = (idx >> 7) % 3;
        int mg = idx / 384;                       // 0..31
        int row = 16 * mg + 8 * (r & 1) + (lane >> 2);   // 0..511
        int kb = ks * 16 + 8 * (r >> 1) + 2 * (lane & 3);
        int n = row >> 5, k = row & 31;
        int node = i0 + n;
        float a0 = 0.f, a1 = 0.f;
        if (k < d_cnt[node] && kb < 36) {
            float el = d_elen[node * KK + k];
            if (kb < 32) {
                float d0 = (el - (float)(kb + 1) * step) * istep;
                float d1 = (el - (float)(kb + 2) * step) * istep;
                a0 = expf(-d0 * d0) * (1.f / 1.12f);
                a1 = expf(-d1 * d1) * (1.f / 1.12f);
            } else {
                int s = d_nbr[node * KK + k];
                float inv = 1.f / el;
                float ex = coords[s * 3 + 0] - coords[node * 3 + 0];
                float ey = coords[s * 3 + 1] - coords[node * 3 + 1];
                float ez = coords[s * 3 + 2] - coords[node * 3 + 2];
                if (kb == 32) { a0 = ex * inv; a1 = ey * inv; }
                else          { a0 = ez * inv; a1 = 1.0f; }   // kb == 34
            }
        }
        float h0 = __bfloat162float(__float2bfloat16_rn(a0));
        float h1 = __bfloat162float(__float2bfloat16_rn(a1));
        outp[idx]         = pack_bf16x2(h0, h1);
        outp[idx + 12288] = pack_bf16x2(a0 - h0, a1 - h1);
    }
}

// ---------------- B fragments for k_edge: We (+be as row 35) --------------
__global__ void __launch_bounds__(256) k_befrag(const float* __restrict__ We,
                                                const float* __restrict__ be) {
    int cc = blockIdx.x, l = blockIdx.y;
    const float* w = We + (size_t)l * EDIM * X2H;
    const float* bp = be + (size_t)l * X2H;
    unsigned* outp = d_bfrag + (size_t)(l * 4 + cc) * 6144;
    for (int idx = threadIdx.x; idx < 3072; idx += 256) {
        int q = idx & 3;
        int ts = q >> 1, rb = q & 1;
        int lane = (idx >> 2) & 31;
        int tp = (idx >> 7) & 7;
        int ks = idx >> 10;
        int tile = 2 * tp + ts;
        int kb = ks * 16 + 8 * rb + 2 * (lane & 3);
        int gcol = cc * 128 + tile * 8 + (lane >> 2);
        float b0 = (kb < EDIM) ? w[kb * X2H + gcol] : ((kb == 35) ? bp[gcol] : 0.f);
        int kb1 = kb + 1;
        float b1 = (kb1 < EDIM) ? w[kb1 * X2H + gcol] : ((kb1 == 35) ? bp[gcol] : 0.f);
        float h0 = __bfloat162float(__float2bfloat16_rn(b0));
        float h1 = __bfloat162float(__float2bfloat16_rn(b1));
        outp[idx]        = pack_bf16x2(h0, h1);
        outp[idx + 3072] = pack_bf16x2(b0 - h0, b1 - h1);
    }
}

// ---------------- weight fragments for MLP GEMMs (device-symbol dst) ------
template <int KS>
__global__ void __launch_bounds__(256) k_wfrag(const float* __restrict__ W) {
    int ksg = blockIdx.x, l = blockIdx.y;
    const float* wl = W + (size_t)l * KS * 16 * HH;
    unsigned* dl = ((KS == 32) ? d_w1frag : d_w2frag) + (size_t)l * KS * 4096;
    for (int idx = threadIdx.x; idx < 2048; idx += 256) {
        int ntg = idx >> 6;
        int lane = (idx >> 1) & 31;
        int tt = idx & 1;
        int kb = ksg * 16 + 8 * tt + 2 * (lane & 3);
        int col = ntg * 8 + (lane >> 2);
        float b0 = wl[(size_t)kb * HH + col];
        float b1 = wl[(size_t)(kb + 1) * HH + col];
        float h0 = __bfloat162float(__float2bfloat16_rn(b0));
        float h1 = __bfloat162float(__float2bfloat16_rn(b1));
        dl[(size_t)ksg * 2048 + idx] = pack_bf16x2(h0, h1);
        dl[(size_t)KS * 2048 + (size_t)ksg * 2048 + idx] = pack_bf16x2(b0 - h0, b1 - h1);
    }
}

// ---------------- k_edge: 16 nodes/block, fully-resident A+B, 1 sync ------
#define OFF_AF   0        // A hi|lo : 24576 words
#define OFF_BF   24576    // B all 4 chunks: 24576 words
#define OFF_STP  49152    // 256
#define SMEM_EDGE_WORDS 49408

__global__ void __launch_bounds__(256) k_edge(int l) {
    extern __shared__ float sm[];
    unsigned* Af = (unsigned*)sm + OFF_AF;
    unsigned* Bf = (unsigned*)sm + OFF_BF;
    float* stp = sm + OFF_STP;
    __shared__ int ssrc[16][32];
    __shared__ int scnt[16];

    int t = threadIdx.x;
    int w = t >> 5, lane = t & 31;
    int i0 = blockIdx.x * 16;
    int g = i0 >> 9;

    for (int e = t; e < 512; e += 256) {   // 16 nodes x 32 entries
        int n = e >> 5, k = e & 31;
        int c = d_cnt[i0 + n];
        if (k == 0) scnt[n] = c;
        ssrc[n][k] = (k < c) ? d_nbr[(i0 + n) * KK + k] : (i0 + n);
    }
    stp[t] = d_tproj[(l * BB + g) * HH + t];  // t<256

    {   // stage A (6144 uint4) + all B chunks (6144 uint4)
        const uint4* asrc = (const uint4*)(d_afrag + (size_t)blockIdx.x * 24576);
        uint4* adst = (uint4*)Af;
        for (int idx = t; idx < 6144; idx += 256) adst[idx] = asrc[idx];
        const uint4* bsrc = (const uint4*)(d_bfrag + (size_t)l * 24576);
        uint4* bdst = (uint4*)Bf;
        for (int idx = t; idx < 6144; idx += 256) bdst[idx] = bsrc[idx];
    }
    __syncthreads();   // the ONLY block-wide sync

    #pragma unroll
    for (int nn = 0; nn < 2; nn++) {
        int node = 2 * w + nn;                 // warp owns nodes 2w, 2w+1
        int cnt_n = scnt[node];
        int rr = lane >> 2;
        int s0 = ssrc[node][rr],      s1 = ssrc[node][rr + 8];
        int s2 = ssrc[node][rr + 16], s3 = ssrc[node][rr + 24];
        float mk0 = (rr      < cnt_n) ? 1.f : 0.f;
        float mk1 = (rr + 8  < cnt_n) ? 1.f : 0.f;
        float mk2 = (rr + 16 < cnt_n) ? 1.f : 0.f;
        float mk3 = (rr + 24 < cnt_n) ? 1.f : 0.f;
        int mg0 = 2 * node, mg1 = 2 * node + 1;

        for (int cc = 0; cc < 4; cc++) {
            unsigned* Bfc = Bf + cc * 6144;
            #pragma unroll
            for (int p = 0; p < 2; p++) {
                float acc[2][8][4];
                #pragma unroll
                for (int m = 0; m < 2; m++)
                    #pragma unroll
                    for (int q = 0; q < 8; q++) {
                        acc[m][q][0] = 0.f; acc[m][q][1] = 0.f;
                        acc[m][q][2] = 0.f; acc[m][q][3] = 0.f;
                    }
                #pragma unroll
                for (int ks = 0; ks < 3; ks++) {
                    uint4 ah0 = *(const uint4*)&Af[((mg0 * 3 + ks) * 32 + lane) * 4];
                    uint4 al0 = *(const uint4*)&Af[12288 + ((mg0 * 3 + ks) * 32 + lane) * 4];
                    uint4 ah1 = *(const uint4*)&Af[((mg1 * 3 + ks) * 32 + lane) * 4];
                    uint4 al1 = *(const uint4*)&Af[12288 + ((mg1 * 3 + ks) * 32 + lane) * 4];
                    #pragma unroll
                    for (int tt = 0; tt < 4; tt++) {
                        int tp = p * 4 + tt;
                        uint4 bh = *(const uint4*)&Bfc[((ks * 8 + tp) * 32 + lane) * 4];
                        uint4 bl = *(const uint4*)&Bfc[3072 + ((ks * 8 + tp) * 32 + lane) * 4];
                        mma_bf16(acc[0][2 * tt + 0], ah0, bh.x, bh.y);
                        mma_bf16(acc[0][2 * tt + 0], al0, bh.x, bh.y);
                        mma_bf16(acc[0][2 * tt + 0], ah0, bl.x, bl.y);
                        mma_bf16(acc[0][2 * tt + 1], ah0, bh.z, bh.w);
                        mma_bf16(acc[0][2 * tt + 1], al0, bh.z, bh.w);
                        mma_bf16(acc[0][2 * tt + 1], ah0, bl.z, bl.w);
                        mma_bf16(acc[1][2 * tt + 0], ah1, bh.x, bh.y);
                        mma_bf16(acc[1][2 * tt + 0], al1, bh.x, bh.y);
                        mma_bf16(acc[1][2 * tt + 0], ah1, bl.x, bl.y);
                        mma_bf16(acc[1][2 * tt + 1], ah1, bh.z, bh.w);
                        mma_bf16(acc[1][2 * tt + 1], al1, bh.z, bh.w);
                        mma_bf16(acc[1][2 * tt + 1], ah1, bl.z, bl.w);
                    }
                }

                #pragma unroll
                for (int nt = 0; nt < 8; nt++) {
                    int gcol = cc * 128 + p * 64 + nt * 8 + 2 * (lane & 3);
                    float2 x0, x1, x2, x3;
                    if (cc < 2) {
                        x0 = *(const float2*)(d_h + (size_t)s0 * HH + gcol);
                        x1 = *(const float2*)(d_h + (size_t)s1 * HH + gcol);
                        x2 = *(const float2*)(d_h + (size_t)s2 * HH + gcol);
                        x3 = *(const float2*)(d_h + (size_t)s3 * HH + gcol);
                    } else {
                        float2 tv = *(const float2*)&stp[gcol - HH];
                        x0 = tv; x1 = tv; x2 = tv; x3 = tv;
                    }
                    float sA = mk0 * fmaxf(acc[0][nt][0] + x0.x, 0.f);
                    sA = fmaf(mk1, fmaxf(acc[0][nt][2] + x1.x, 0.f), sA);
                    sA = fmaf(mk2, fmaxf(acc[1][nt][0] + x2.x, 0.f), sA);
                    sA = fmaf(mk3, fmaxf(acc[1][nt][2] + x3.x, 0.f), sA);
                    float sB = mk0 * fmaxf(acc[0][nt][1] + x0.y, 0.f);
                    sB = fmaf(mk1, fmaxf(acc[0][nt][3] + x1.y, 0.f), sB);
                    sB = fmaf(mk2, fmaxf(acc[1][nt][1] + x2.y, 0.f), sB);
                    sB = fmaf(mk3, fmaxf(acc[1][nt][3] + x3.y, 0.f), sB);
                    #pragma unroll
                    for (int off = 16; off >= 4; off >>= 1) {
                        sA += __shfl_down_sync(0xffffffffu, sA, off);
                        sB += __shfl_down_sync(0xffffffffu, sB, off);
                    }
                    if (lane < 4) {
                        int gc = cc * 128 + p * 64 + nt * 8 + 2 * lane;
                        *(float2*)(d_aggr + (size_t)(i0 + node) * X2H + gc) = make_float2(sA, sB);
                    }
                }
            }
        }
    }
}

// ---------------- tensor-core MLP GEMM (wide: 64 rows x 128 cols) ---------
// grid (2, 64); 8 warps = 4 m-tiles x 2 col-64-halves (8 n-tiles each).
// MODE0: z1 = silu(((1+eps)*[h|tproj] + aggr) @ W1 + b1)   K=512
// MODE1: z  = z1 @ W2 + b2 (+ GraphNorm col partials)       K=256
#define SMEM_G_WORDS 12544

template <int MODE>
__global__ void __launch_bounds__(256) k_mgemm(const float* __restrict__ bias,
                                               const float* __restrict__ epsp, int l) {
    const int KS = (MODE == 0) ? 32 : 16;
    const int NKSC = KS / 4;
    extern __shared__ float sm[];
    unsigned* Af = (unsigned*)sm;          // hi 0..2048, lo 2048..4096
    unsigned* Bf = (unsigned*)sm + 4096;   // hi 0..4096, lo 4096..8192
    float* stp = sm + 12288;               // 256
    int t = threadIdx.x;
    int w = t >> 5, lane = t & 31;
    int bx = blockIdx.x, mb = blockIdx.y;  // bx in {0,1}: 128-col half
    int m0 = mb * 64;
    int g = m0 >> 9;
    float ep = (MODE == 0) ? (1.f + epsp[l]) : 0.f;
    if (MODE == 0 && t < HH) stp[t] = d_tproj[(l * BB + g) * HH + t];
    const unsigned* wl = ((MODE == 0) ? d_w1frag : d_w2frag) + (size_t)l * KS * 4096;
    int mt = w & 3, half = w >> 2;

    float acc[8][4];
    #pragma unroll
    for (int q = 0; q < 8; q++) {
        acc[q][0] = 0.f; acc[q][1] = 0.f; acc[q][2] = 0.f; acc[q][3] = 0.f;
    }

    for (int ksc = 0; ksc < NKSC; ksc++) {
        __syncthreads();
        // stage A: bf16 hi/lo fragments with fused input epilogue
        for (int idx = t; idx < 2048; idx += 256) {
            int mtl = idx >> 9;
            int rem = idx & 511;
            int ksl = rem >> 7;
            int ln = (rem >> 2) & 31;
            int r = idx & 3;
            int row = m0 + 16 * mtl + 8 * (r & 1) + (ln >> 2);
            int kb = ksc * 64 + ksl * 16 + 8 * (r >> 1) + 2 * (ln & 3);
            float v0, v1;
            if (MODE == 0) {
                float2 ag = *(const float2*)(d_aggr + (size_t)row * X2H + kb);
                float2 hx;
                if (kb < HH) hx = *(const float2*)(d_h + (size_t)row * HH + kb);
                else         hx = *(const float2*)&stp[kb - HH];
                v0 = fmaf(ep, hx.x, ag.x);
                v1 = fmaf(ep, hx.y, ag.y);
            } else {
                float2 zz = *(const float2*)(d_z1 + (size_t)row * HH + kb);
                v0 = zz.x; v1 = zz.y;
            }
            float h0 = __bfloat162float(__float2bfloat16_rn(v0));
            float h1 = __bfloat162float(__float2bfloat16_rn(v1));
            Af[idx]        = pack_bf16x2(h0, h1);
            Af[idx + 2048] = pack_bf16x2(v0 - h0, v1 - h1);
        }
        // stage B: 128-col slice of precomputed weight fragments (1 uint4/thr/region)
        #pragma unroll
        for (int ks4 = 0; ks4 < 4; ks4++) {
            int ksg = ksc * 4 + ks4;
            const uint4* sh = (const uint4*)(wl + (size_t)ksg * 2048 + bx * 1024);
            const uint4* sl = (const uint4*)(wl + (size_t)KS * 2048 +
                                             (size_t)ksg * 2048 + bx * 1024);
            ((uint4*)(Bf + ks4 * 1024))[t] = sh[t];
            ((uint4*)(Bf + 4096 + ks4 * 1024))[t] = sl[t];
        }
        __syncthreads();
        #pragma unroll
        for (int ks = 0; ks < 4; ks++) {
            uint4 ah = *(const uint4*)&Af[((mt * 4 + ks) * 32 + lane) * 4];
            uint4 al = *(const uint4*)&Af[2048 + ((mt * 4 + ks) * 32 + lane) * 4];
            #pragma unroll
            for (int j = 0; j < 8; j++) {
                int ntl = half * 8 + j;
                uint2 bh = *(const uint2*)&Bf[ks * 1024 + ntl * 64 + lane * 2];
                uint2 bl = *(const uint2*)&Bf[4096 + ks * 1024 + ntl * 64 + lane * 2];
                mma_bf16(acc[j], ah, bh.x, bh.y);
                mma_bf16(acc[j], al, bh.x, bh.y);
                mma_bf16(acc[j], ah, bl.x, bl.y);
            }
        }
    }
    __syncthreads();

    int r0 = m0 + mt * 16 + (lane >> 2);
    if (MODE == 0) {
        #pragma unroll
        for (int j = 0; j < 8; j++) {
            int col = bx * 128 + (half * 8 + j) * 8 + 2 * (lane & 3);
            float b0v = bias[col], b1v = bias[col + 1];
            *(float2*)(d_z1 + (size_t)r0 * HH + col) =
                make_float2(silu_f(acc[j][0] + b0v), silu_f(acc[j][1] + b1v));
            *(float2*)(d_z1 + (size_t)(r0 + 8) * HH + col) =
                make_float2(silu_f(acc[j][2] + b0v), silu_f(acc[j][3] + b1v));
        }
    } else {
        float* sps = sm;          // reuse Af region: 4*128 + 4*128 floats
        float* spq = sm + 512;
        #pragma unroll
        for (int j = 0; j < 8; j++) {
            int cl = (half * 8 + j) * 8 + 2 * (lane & 3);
            int col = bx * 128 + cl;
            float b0v = bias[col], b1v = bias[col + 1];
            float v00 = acc[j][0] + b0v, v01 = acc[j][1] + b1v;
            float v10 = acc[j][2] + b0v, v11 = acc[j][3] + b1v;
            *(float2*)(d_z + (size_t)r0 * HH + col) = make_float2(v00, v01);
            *(float2*)(d_z + (size_t)(r0 + 8) * HH + col) = make_float2(v10, v11);
            float s0 = v00 + v10, s1 = v01 + v11;
            float q0 = v00 * v00 + v10 * v10, q1 = v01 * v01 + v11 * v11;
            #pragma unroll
            for (int off = 16; off >= 4; off >>= 1) {
                s0 += __shfl_down_sync(0xffffffffu, s0, off);
                s1 += __shfl_down_sync(0xffffffffu, s1, off);
                q0 += __shfl_down_sync(0xffffffffu, q0, off);
                q1 += __shfl_down_sync(0xffffffffu, q1, off);
            }
            if (lane < 4) {
                int c2 = (half * 8 + j) * 8 + 2 * lane;
                sps[mt * 128 + c2] = s0; sps[mt * 128 + c2 + 1] = s1;
                spq[mt * 128 + c2] = q0; spq[mt * 128 + c2 + 1] = q1;
            }
        }
        __syncthreads();
        if (t < 128) {
            float S = 0.f, Q = 0.f;
            #pragma unroll
            for (int p = 0; p < 4; p++) { S += sps[p * 128 + t]; Q += spq[p * 128 + t]; }
            d_psum[mb * HH + bx * 128 + t] = S;
            d_psumq[mb * HH + bx * 128 + t] = Q;
        }
    }
}

// ---------------- GraphNorm finalize (folds gemm1 partials) ---------------
// grid 128 blocks x 32 rows
__global__ void k_gfin(const float* __restrict__ gw, const float* __restrict__ gb,
                       const float* __restrict__ gms) {
    int nb = blockIdx.x * 32;
    int g = nb >> 9;
    int c = threadIdx.x;
    float s = 0.f, q = 0.f;
    #pragma unroll
    for (int p = 0; p < 8; p++) {
        s += d_psum[(g * 8 + p) * HH + c];
        q += d_psumq[(g * 8 + p) * HH + c];
    }
    float mean = s * (1.f / 512.f);
    float ez2  = q * (1.f / 512.f);
    float mm = mean * gms[c];
    float var = ez2 - 2.f * mm * mean + mm * mm;
    float inv = 1.f / sqrtf(var + 1e-5f);
    float w = gw[c], b = gb[c];
    for (int n = 0; n < 32; n++) {
        size_t id = (size_t)(nb + n) * HH + c;
        float cc = d_z[id] - mm;
        float zn = fmaf(w * cc, inv, b);
        float hv = zn + d_h[id];
        d_h[id] = silu_f(hv);
    }
}

// ---------------- output head ----------------
__global__ void k_out(const float* __restrict__ Wout, const float* __restrict__ bout,
                      float* __restrict__ out) {
    __shared__ float sw[HH * 3];
    int t = threadIdx.x;
    for (int idx = t; idx < HH * 3; idx += 256) sw[idx] = Wout[idx];
    __syncthreads();
    int w = t >> 5, lane = t & 31;
    int i = blockIdx.x * 8 + w;
    float a0 = 0.f, a1 = 0.f, a2 = 0.f;
    for (int c = lane; c < HH; c += 32) {
        float hv = d_h[(size_t)i * HH + c];
        a0 = fmaf(hv, sw[c * 3 + 0], a0);
        a1 = fmaf(hv, sw[c * 3 + 1], a1);
        a2 = fmaf(hv, sw[c * 3 + 2], a2);
    }
    #pragma unroll
    for (int off = 16; off; off >>= 1) {
        a0 += __shfl_down_sync(0xffffffffu, a0, off);
        a1 += __shfl_down_sync(0xffffffffu, a1, off);
        a2 += __shfl_down_sync(0xffffffffu, a2, off);
    }
    if (lane == 0) {
        out[i * 3 + 0] = a0 + bout[0];
        out[i * 3 + 1] = a1 + bout[1];
        out[i * 3 + 2] = a2 + bout[2];
    }
}

// -------------------------------------------------------------------------
extern "C" void kernel_launch(void* const* d_in, const int* in_sizes, int n_in,
                              void* d_out, int out_size) {
    const float* coords = (const float*)d_in[0];
    const float* tin  = (const float*)d_in[2];
    const float* Wgfp = (const float*)d_in[3];
    const float* Wt_  = (const float*)d_in[4];
    const float* bt_  = (const float*)d_in[5];
    const float* Win  = (const float*)d_in[6];
    const float* bin  = (const float*)d_in[7];
    const float* W1   = (const float*)d_in[8];
    const float* b1   = (const float*)d_in[9];
    const float* W2   = (const float*)d_in[10];
    const float* b2   = (const float*)d_in[11];
    const float* We   = (const float*)d_in[12];
    const float* be   = (const float*)d_in[13];
    const float* eps  = (const float*)d_in[14];
    const float* gnw  = (const float*)d_in[15];
    const float* gnb  = (const float*)d_in[16];
    const float* gnms = (const float*)d_in[17];
    const float* Wtl  = (const float*)d_in[18];
    const float* btl  = (const float*)d_in[19];
    const float* Wout = (const float*)d_in[20];
    const float* bout = (const float*)d_in[21];
    float* out = (float*)d_out;

    const int smem_edge = SMEM_EDGE_WORDS * 4;   // 197632 B
    const int smem_g = SMEM_G_WORDS * 4;         // 50176 B
    cudaFuncSetAttribute(k_edge, cudaFuncAttributeMaxDynamicSharedMemorySize, smem_edge);
    cudaFuncSetAttribute(k_mgemm<0>, cudaFuncAttributeMaxDynamicSharedMemorySize, smem_g);
    cudaFuncSetAttribute(k_mgemm<1>, cudaFuncAttributeMaxDynamicSharedMemorySize, smem_g);

    k_temb<<<1, 128>>>(tin, Wgfp, Wt_, bt_);
    k_tproj<<<LL * BB, 256>>>(Wtl, btl);
    k_hin<<<NN, 256>>>(coords, Win, bin);
    k_nbr<<<NN / 4, 128>>>(coords);
    k_afrag<<<NN / 16, 256>>>(coords);
    k_befrag<<<dim3(4, LL), 256>>>(We, be);
    k_wfrag<32><<<dim3(32, LL), 256>>>(W1);
    k_wfrag<16><<<dim3(16, LL), 256>>>(W2);

    for (int l = 0; l < LL; l++) {
        k_edge<<<NN / 16, 256, smem_edge>>>(l);
        k_mgemm<0><<<dim3(2, 64), 256, smem_g>>>(b1 + l * HH, eps, l);
        k_mgemm<1><<<dim3(2, 64), 256, smem_g>>>(b2 + l * HH, eps, l);
        k_gfin<<<128, 256>>>(gnw + l * HH, gnb + l * HH, gnms + l * HH);
    }
    k_out<<<NN / 8, 256>>>(Wout, bout, out);
}